// round 9
// baseline (speedup 1.0000x reference)
#include <cuda_runtime.h>
#include <cstdint>

#define OC 64
#define IC 208
#define EPSV 1e-5f
#define PD 38
#define PH 38
#define PW 40
#define PCH (PD * PH * PW)
#define KTAPS 352
#define NK16 22
#define CHUNK_U4 256                  // uint4 per k16 B-chunk
#define BCH_U4 (NK16 * CHUNK_U4)      // 5632 uint4 per channel
#define HCH 11                        // chunks per half
#define INW 16                        // input row width (floats)
#define INWORDS (189 * INW)           // 3024 floats per input buffer

__device__ float g_P[(size_t)4 * IC * PCH];
__device__ uint4 g_W[(size_t)IC * BCH_U4];     // [c][q][nblk][lane] = {b0h,b1h,b0l,b1l}
__device__ float g_ss[OC];
__device__ float g_scale[OC];

// ---------------- helpers ----------------
static __device__ __forceinline__ uint32_t pack_bf16x2(float hi, float lo) {
    uint32_t r; asm("cvt.rn.bf16x2.f32 %0, %1, %2;" : "=r"(r) : "f"(hi), "f"(lo));
    return r;
}
static __device__ __forceinline__ void unpack_bf16x2(uint32_t p, float& lo, float& hi) {
    lo = __uint_as_float(p << 16);
    hi = __uint_as_float(p & 0xffff0000u);
}
static __device__ __forceinline__ void mma_bf16(float* d, const uint32_t* a,
                                                uint32_t b0, uint32_t b1) {
    asm volatile("mma.sync.aligned.m16n8k16.row.col.f32.bf16.bf16.f32 "
        "{%0,%1,%2,%3}, {%4,%5,%6,%7}, {%8,%9}, {%0,%1,%2,%3};"
        : "+f"(d[0]), "+f"(d[1]), "+f"(d[2]), "+f"(d[3])
        : "r"(a[0]), "r"(a[1]), "r"(a[2]), "r"(a[3]), "r"(b0), "r"(b1));
}

#define CPA(dst, src) asm volatile("cp.async.cg.shared.global [%0], [%1], 16;" :: "r"(dst), "l"(src))
#define CPC() asm volatile("cp.async.commit_group;" ::)
#define CPW0() asm volatile("cp.async.wait_group 0;" ::: "memory")

// ---------------- K1: build weights (identical layout to R7) ----------------
__global__ void build_w_kernel(
    int c0, int c1,
    const float* __restrict__ wss, const float* __restrict__ wsv, const float* __restrict__ wst,
    const float* __restrict__ wvs, const float* __restrict__ wvv, const float* __restrict__ wvt,
    const float* __restrict__ bss, const float* __restrict__ bsv, const float* __restrict__ bst,
    const float* __restrict__ bvs, const float* __restrict__ bvv, const float* __restrict__ bvt) {
    int idx = blockIdx.x * blockDim.x + threadIdx.x;
    int n = (c1 - c0) * KTAPS * 64;
    if (idx >= n) return;
    int oc  = idx & 63;
    int tap = (idx >> 6) % KTAPS;
    int c   = c0 + idx / (KTAPS * 64);

    float val = 0.f;
    if (tap < 343) {
        int u, io, dout;
        if (oc < 16) { u = oc; io = 0; dout = 1; }
        else         { u = (oc - 16) / 3; io = (oc - 16) % 3; dout = 3; }
        int v, ji, din;
        if (c < 16)       { v = c;            ji = 0;            din = 1; }
        else if (c < 64)  { v = (c - 16) / 3; ji = (c - 16) % 3; din = 3; }
        else              { v = (c - 64) / 9; ji = (c - 64) % 9; din = 9; }
        const float* w; const float* bs; int nb;
        if (oc < 16) {
            if (c < 16)      { w = wss; bs = bss; nb = 3; }
            else if (c < 64) { w = wsv; bs = bsv; nb = 3; }
            else             { w = wst; bs = bst; nb = 9; }
        } else {
            if (c < 16)      { w = wvs; bs = bvs; nb = 3; }
            else if (c < 64) { w = wvv; bs = bvv; nb = 9; }
            else             { w = wvt; bs = bvt; nb = 21; }
        }
        for (int bb = 0; bb < nb; bb++)
            val = fmaf(w[(u * 16 + v) * nb + bb],
                       bs[((bb * dout + io) * din + ji) * 343 + tap], val);
    }
    uint32_t hp = pack_bf16x2(0.f, val);
    float hf = __uint_as_float(hp << 16);
    uint32_t lp = pack_bf16x2(0.f, val - hf);
    uint16_t hb = (uint16_t)(hp & 0xffff);
    uint16_t lb = (uint16_t)(lp & 0xffff);

    int q = tap >> 4, kk = tap & 15;
    int j = oc >> 3;
    int lane = ((oc & 7) << 2) + ((kk & 7) >> 1);
    size_t u4 = ((size_t)c * NK16 + q) * CHUNK_U4 + j * 32 + lane;
    uint16_t* h16 = (uint16_t*)&g_W[u4];
    int word = kk >> 3, half = kk & 1;
    h16[word * 2 + half]     = hb;
    h16[4 + word * 2 + half] = lb;
}

// ---------------- K2: padded svt ----------------
__global__ void pad_kernel(const float* __restrict__ sv) {
    long long idx = (long long)blockIdx.x * 256 + threadIdx.x;
    if (idx >= (long long)4 * IC * PCH) return;
    int bc = (int)(idx / PCH);
    int r  = (int)(idx - (long long)bc * PCH);
    int b = bc / IC, c = bc % IC;
    int pd = r / (PH * PW); r -= pd * (PH * PW);
    int ph = r / PW;
    int pw = r - ph * PW;
    int id = pd - 3, ih = ph - 3, iw = pw - 3;
    float val = 0.f;
    if ((unsigned)id < 32u && (unsigned)ih < 32u && (unsigned)iw < 32u) {
        int off = id * 1024 + ih * 32 + iw;
        const float* svb = sv + (size_t)b * 64 * 32768;
        if (c < 64) val = svb[(size_t)c * 32768 + off];
        else {
            int cc = c - 64, u = cc / 9, comp = cc % 9;
            val = svb[(size_t)(16 + u * 3 + comp / 3) * 32768 + off] *
                  svb[(size_t)(16 + u * 3 + comp % 3) * 32768 + off];
        }
    }
    g_P[idx] = val;
}

// ---------------- K3: mma.sync bf16x3, tile M=64, 2 CTAs/SM ----------------
// 256 thr = 8 warps = 4 Mg x 2 Nh. Warp: 16 voxels x 32 oc.
// smem floats: tap4[88*4=352] | in 2x3024 | B ring 2x(11*1024)
extern __shared__ float smem[];

__global__ void __launch_bounds__(256, 2)
conv_kernel(float* __restrict__ out) {
    uint4* tap4 = (uint4*)smem;                         // [q][c4]
    float* s_in = smem + 352;
    uint4* s_B  = (uint4*)(smem + 352 + 2 * INWORDS);   // 2 slots x 11 chunks

    const int tid = threadIdx.x, lane = tid & 31, w = tid >> 5;
    const int mg = w & 3, nh = w >> 2;
    const int tt = blockIdx.x, b = blockIdx.y;
    const int td = (tt >> 3) * 2, th = ((tt >> 2) & 1) * 8, tw = (tt & 3) * 4;

    // tap offset table: o(t) in input-tile floats (d-slab 336, h-row 16)
    for (int e = tid; e < 88; e += 256) {
        int q = e >> 2, c4 = e & 3;
        int o[4];
        for (int s = 0; s < 4; s++) {
            int kk = (s & 1) + 2 * c4 + (s >> 1) * 8;
            int t = q * 16 + kk;
            if (t >= 343) { o[s] = 0; continue; }
            int kd = t / 49, r = t % 49, kh = r / 7, kw = r % 7;
            o[s] = kd * 336 + kh * 16 + kw;
        }
        tap4[e] = make_uint4(o[0], o[1], o[2], o[3]);
    }

    const int c4 = lane & 3;
    const int m0 = mg * 16 + (lane >> 2), m1 = m0 + 8;
    // voxel m: vd = m>>5, vh = (m>>2)&7, vw = m&3 ; g = 2vd*336 + 2vh*16 + 2vw
    const int g0 = (m0 >> 5) * 672 + ((m0 >> 2) & 7) * 32 + (m0 & 3) * 2;
    const int g1 = (m1 >> 5) * 672 + ((m1 >> 2) & 7) * 32 + (m1 & 3) * 2;

    const uint32_t inb = (uint32_t)__cvta_generic_to_shared(s_in);
    const uint32_t Bb  = (uint32_t)__cvta_generic_to_shared(s_B);

    // stage half h = 2c + hf : B chunks [hf*11, hf*11+11) into slot hf; input(c) with hf==0
    auto stage = [&](int h) {
        int c = h >> 1, hf = h & 1;
        const uint4* bsrc = g_W + (size_t)c * BCH_U4 + hf * HCH * CHUNK_U4;
        uint32_t dstb = Bb + (uint32_t)hf * (HCH * CHUNK_U4) * 16;
        for (int i = tid; i < HCH * CHUNK_U4; i += 256) CPA(dstb + i * 16, bsrc + i);
        if (hf == 0) {
            const float* src = g_P + ((size_t)b * IC + c) * PCH
                             + (2 * td) * (PH * PW) + (2 * th) * PW + (2 * tw);
            uint32_t dsti = inb + (uint32_t)(c & 1) * INWORDS * 4;
            for (int i = tid; i < 189 * 4; i += 256) {
                int row = i >> 2, seg = i & 3;
                int dd = row / 21, dh = row - dd * 21;
                CPA(dsti + (row * INW + seg * 4) * 4,
                    src + dd * (PH * PW) + dh * PW + seg * 4);
            }
        }
    };

    float acc[4][4];
#pragma unroll
    for (int j = 0; j < 4; j++)
#pragma unroll
        for (int k = 0; k < 4; k++) acc[j][k] = 0.f;

    __syncthreads();          // tap table ready
    stage(0); CPC();

    for (int h = 0; h < 2 * IC; h++) {
        CPW0();
        __syncthreads();
        if (h + 1 < 2 * IC) { stage(h + 1); CPC(); }

        const int c = h >> 1, hf = h & 1;
        const float* si = s_in + (c & 1) * INWORDS;
        const uint4* Bs = s_B + hf * (HCH * CHUNK_U4);

#pragma unroll 1
        for (int ql = 0; ql < HCH; ql++) {
            const int q = hf * HCH + ql;
            uint4 o = tap4[q * 4 + c4];
            float f0 = si[g0 + o.x], f1 = si[g0 + o.y];
            float f2 = si[g1 + o.x], f3 = si[g1 + o.y];
            float f4 = si[g0 + o.z], f5 = si[g0 + o.w];
            float f6 = si[g1 + o.z], f7 = si[g1 + o.w];

            uint32_t ah[4], al[4];
            ah[0] = pack_bf16x2(f1, f0); ah[1] = pack_bf16x2(f3, f2);
            ah[2] = pack_bf16x2(f5, f4); ah[3] = pack_bf16x2(f7, f6);
            float hl, hh;
            unpack_bf16x2(ah[0], hl, hh); al[0] = pack_bf16x2(f1 - hh, f0 - hl);
            unpack_bf16x2(ah[1], hl, hh); al[1] = pack_bf16x2(f3 - hh, f2 - hl);
            unpack_bf16x2(ah[2], hl, hh); al[2] = pack_bf16x2(f5 - hh, f4 - hl);
            unpack_bf16x2(ah[3], hl, hh); al[3] = pack_bf16x2(f7 - hh, f6 - hl);

            const uint4* Bq = Bs + ql * CHUNK_U4 + nh * 128 + lane;
#pragma unroll
            for (int j = 0; j < 4; j++) {
                uint4 bb = Bq[j * 32];
                mma_bf16(acc[j], ah, bb.x, bb.y);   // Ah*Bh
                mma_bf16(acc[j], al, bb.x, bb.y);   // Al*Bh
                mma_bf16(acc[j], ah, bb.z, bb.w);   // Ah*Bl
            }
        }
        __syncthreads();
    }

    // epilogue: rows m0/m1, cols (nh*4+j)*8 + 2*c4 (+1)
    const int od0 = td + (m0 >> 5), oh0 = th + ((m0 >> 2) & 7), ow0 = tw + (m0 & 3);
    const int od1 = td + (m1 >> 5), oh1 = th + ((m1 >> 2) & 7), ow1 = tw + (m1 & 3);
    float* ob = out + (size_t)b * OC * 4096;
    const int v0 = od0 * 256 + oh0 * 16 + ow0;
    const int v1 = od1 * 256 + oh1 * 16 + ow1;
#pragma unroll
    for (int j = 0; j < 4; j++) {
        int oc0 = (nh * 4 + j) * 8 + 2 * c4;
        ob[(size_t)oc0 * 4096 + v0]       = acc[j][0];
        ob[(size_t)(oc0 + 1) * 4096 + v0] = acc[j][1];
        ob[(size_t)oc0 * 4096 + v1]       = acc[j][2];
        ob[(size_t)(oc0 + 1) * 4096 + v1] = acc[j][3];
    }
}

// ---------------- epilogue kernels ----------------
__global__ void sumsq_kernel(const float* __restrict__ y) {
    __shared__ float red[256];
    const int ch = blockIdx.x, tid = threadIdx.x;
    float s = 0.f;
    for (int i = tid; i < 4 * 4096; i += 256) {
        int b = i >> 12, sp = i & 4095;
        float v = y[((size_t)b * OC + ch) * 4096 + sp];
        s = fmaf(v, v, s);
    }
    red[tid] = s;
    __syncthreads();
    for (int o = 128; o > 0; o >>= 1) {
        if (tid < o) red[tid] += red[tid + o];
        __syncthreads();
    }
    if (tid == 0) g_ss[ch] = red[0];
}

__global__ void finalize_kernel(const float* __restrict__ bngs, const float* __restrict__ bngv) {
    int ch = threadIdx.x;
    float sc;
    if (ch < 16) sc = bngs[ch] / sqrtf(g_ss[ch] / 16384.f + EPSV);
    else {
        int u = (ch - 16) / 3;
        sc = bngv[u] / sqrtf((g_ss[16 + 3 * u] + g_ss[17 + 3 * u] + g_ss[18 + 3 * u]) / 49152.f + EPSV);
    }
    g_scale[ch] = sc;
}

__global__ void scale_act_kernel(float* __restrict__ y, const float* __restrict__ bias) {
    int i = blockIdx.x * 256 + threadIdx.x;
    int ch = (i >> 12) & 63;
    float v = y[i] * g_scale[ch];
    if (ch < 16) v = fmaxf(v + bias[ch], 0.f);
    y[i] = v;
}

// ---------------- launch ----------------
extern "C" void kernel_launch(void* const* d_in, const int* in_sizes, int n_in,
                              void* d_out, int out_size) {
    const float* sv = (const float*)d_in[0];
    const float *wss, *wsv, *wst, *wvs, *wvv, *wvt;
    const float *bss, *bsv, *bst, *bvs, *bvv, *bvt;
    if (in_sizes[1] == 1029) {
        bss = (const float*)d_in[1];  wss = (const float*)d_in[2];
        bsv = (const float*)d_in[3];  wsv = (const float*)d_in[4];
        bst = (const float*)d_in[5];  wst = (const float*)d_in[6];
        bvs = (const float*)d_in[7];  wvs = (const float*)d_in[8];
        bvv = (const float*)d_in[9];  wvv = (const float*)d_in[10];
        bvt = (const float*)d_in[11]; wvt = (const float*)d_in[12];
    } else {
        wss = (const float*)d_in[1];  wsv = (const float*)d_in[2];  wst = (const float*)d_in[3];
        wvs = (const float*)d_in[4];  wvv = (const float*)d_in[5];  wvt = (const float*)d_in[6];
        bss = (const float*)d_in[7];  bsv = (const float*)d_in[8];  bst = (const float*)d_in[9];
        bvs = (const float*)d_in[10]; bvv = (const float*)d_in[11]; bvt = (const float*)d_in[12];
    }
    const float* bngs = (const float*)d_in[13];
    const float* bngv = (const float*)d_in[14];
    const float* bias = (const float*)d_in[15];
    float* out = (float*)d_out;

    // smem: 352 + 2*3024 + 2*11*1024 floats = 28,928 floats = 115,712 B  (2 CTAs/SM)
    const int SMEM_BYTES = (352 + 2 * INWORDS + 2 * HCH * 1024) * 4;
    cudaFuncSetAttribute(conv_kernel, cudaFuncAttributeMaxDynamicSharedMemorySize, SMEM_BYTES);

    int n1 = 104 * KTAPS * 64;
    build_w_kernel<<<(n1 + 255) / 256, 256>>>(0, 104, wss, wsv, wst, wvs, wvv, wvt,
                                              bss, bsv, bst, bvs, bvv, bvt);
    build_w_kernel<<<(n1 + 255) / 256, 256>>>(104, 208, wss, wsv, wst, wvs, wvv, wvt,
                                              bss, bsv, bst, bvs, bvv, bvt);
    long long nP = (long long)4 * IC * PCH;
    pad_kernel<<<(unsigned)((nP + 255) / 256), 256>>>(sv);
    conv_kernel<<<dim3(64, 4), 256, SMEM_BYTES>>>(out);
    sumsq_kernel<<<64, 256>>>(out);
    finalize_kernel<<<1, 64>>>(bngs, bngv);
    scale_act_kernel<<<4096, 256>>>(out, bias);
}

// round 10
// speedup vs baseline: 1.0724x; 1.0724x over previous
#include <cuda_runtime.h>
#include <cstdint>

#define OC 64
#define IC 208
#define EPSV 1e-5f
#define PD 38
#define PH 38
#define PW 40
#define PCH (PD * PH * PW)
#define KTAPS 352
#define NK16 22
#define CHUNK_U4 256
#define BCH_U4 (NK16 * CHUNK_U4)

__device__ float g_P[(size_t)4 * IC * PCH];
__device__ uint4 g_W[(size_t)IC * BCH_U4];     // [c][q][nblk][lane] = {b0h,b1h,b0l,b1l}
__device__ float g_ss[OC];
__device__ float g_scale[OC];

// ---------------- helpers ----------------
static __device__ __forceinline__ uint32_t pack_bf16x2(float hi, float lo) {
    uint32_t r; asm("cvt.rn.bf16x2.f32 %0, %1, %2;" : "=r"(r) : "f"(hi), "f"(lo));
    return r;
}
static __device__ __forceinline__ void unpack_bf16x2(uint32_t p, float& lo, float& hi) {
    lo = __uint_as_float(p << 16);
    hi = __uint_as_float(p & 0xffff0000u);
}
static __device__ __forceinline__ void mma_bf16(float* d, const uint32_t* a,
                                                uint32_t b0, uint32_t b1) {
    asm volatile("mma.sync.aligned.m16n8k16.row.col.f32.bf16.bf16.f32 "
        "{%0,%1,%2,%3}, {%4,%5,%6,%7}, {%8,%9}, {%0,%1,%2,%3};"
        : "+f"(d[0]), "+f"(d[1]), "+f"(d[2]), "+f"(d[3])
        : "r"(a[0]), "r"(a[1]), "r"(a[2]), "r"(a[3]), "r"(b0), "r"(b1));
}

#define CPA(dst, src) asm volatile("cp.async.cg.shared.global [%0], [%1], 16;" :: "r"(dst), "l"(src))
#define CPC() asm volatile("cp.async.commit_group;" ::)
#define CPW1() asm volatile("cp.async.wait_group 1;" ::: "memory")
#define CPW0() asm volatile("cp.async.wait_group 0;" ::: "memory")

// ---------------- K1: build weights into mma B-fragment layout ----------------
__global__ void build_w_kernel(
    int c0, int c1,
    const float* __restrict__ wss, const float* __restrict__ wsv, const float* __restrict__ wst,
    const float* __restrict__ wvs, const float* __restrict__ wvv, const float* __restrict__ wvt,
    const float* __restrict__ bss, const float* __restrict__ bsv, const float* __restrict__ bst,
    const float* __restrict__ bvs, const float* __restrict__ bvv, const float* __restrict__ bvt) {
    int idx = blockIdx.x * blockDim.x + threadIdx.x;
    int n = (c1 - c0) * KTAPS * 64;
    if (idx >= n) return;
    int oc  = idx & 63;
    int tap = (idx >> 6) % KTAPS;
    int c   = c0 + idx / (KTAPS * 64);

    float val = 0.f;
    if (tap < 343) {
        int u, io, dout;
        if (oc < 16) { u = oc; io = 0; dout = 1; }
        else         { u = (oc - 16) / 3; io = (oc - 16) % 3; dout = 3; }
        int v, ji, din;
        if (c < 16)       { v = c;            ji = 0;            din = 1; }
        else if (c < 64)  { v = (c - 16) / 3; ji = (c - 16) % 3; din = 3; }
        else              { v = (c - 64) / 9; ji = (c - 64) % 9; din = 9; }
        const float* w; const float* bs; int nb;
        if (oc < 16) {
            if (c < 16)      { w = wss; bs = bss; nb = 3; }
            else if (c < 64) { w = wsv; bs = bsv; nb = 3; }
            else             { w = wst; bs = bst; nb = 9; }
        } else {
            if (c < 16)      { w = wvs; bs = bvs; nb = 3; }
            else if (c < 64) { w = wvv; bs = bvv; nb = 9; }
            else             { w = wvt; bs = bvt; nb = 21; }
        }
        for (int bb = 0; bb < nb; bb++)
            val = fmaf(w[(u * 16 + v) * nb + bb],
                       bs[((bb * dout + io) * din + ji) * 343 + tap], val);
    }
    uint32_t hp = pack_bf16x2(0.f, val);
    float hf = __uint_as_float(hp << 16);
    uint32_t lp = pack_bf16x2(0.f, val - hf);
    uint16_t hb = (uint16_t)(hp & 0xffff);
    uint16_t lb = (uint16_t)(lp & 0xffff);

    int q = tap >> 4, kk = tap & 15;
    int j = oc >> 3;
    int lane = ((oc & 7) << 2) + ((kk & 7) >> 1);
    size_t u4 = ((size_t)c * NK16 + q) * CHUNK_U4 + j * 32 + lane;
    uint16_t* h16 = (uint16_t*)&g_W[u4];
    int word = kk >> 3, half = kk & 1;
    h16[word * 2 + half]     = hb;
    h16[4 + word * 2 + half] = lb;
}

// ---------------- K2: padded svt ----------------
__global__ void pad_kernel(const float* __restrict__ sv) {
    long long idx = (long long)blockIdx.x * 256 + threadIdx.x;
    if (idx >= (long long)4 * IC * PCH) return;
    int bc = (int)(idx / PCH);
    int r  = (int)(idx - (long long)bc * PCH);
    int b = bc / IC, c = bc % IC;
    int pd = r / (PH * PW); r -= pd * (PH * PW);
    int ph = r / PW;
    int pw = r - ph * PW;
    int id = pd - 3, ih = ph - 3, iw = pw - 3;
    float val = 0.f;
    if ((unsigned)id < 32u && (unsigned)ih < 32u && (unsigned)iw < 32u) {
        int off = id * 1024 + ih * 32 + iw;
        const float* svb = sv + (size_t)b * 64 * 32768;
        if (c < 64) val = svb[(size_t)c * 32768 + off];
        else {
            int cc = c - 64, u = cc / 9, comp = cc % 9;
            val = svb[(size_t)(16 + u * 3 + comp / 3) * 32768 + off] *
                  svb[(size_t)(16 + u * 3 + comp % 3) * 32768 + off];
        }
    }
    g_P[idx] = val;
}

// ---------------- K3: mma.sync bf16x3, K-split across warps ----------------
// 512 thr = 16 warps = 8 M-groups x 2 K-halves. Warp: 16 voxels x 64 oc, 11 q-steps.
extern __shared__ float smem[];

__global__ void __launch_bounds__(512, 1)
conv_kernel(float* __restrict__ out) {
    int*   tapoff = (int*)smem;
    float* s_in   = smem + 352;
    uint4* s_B    = (uint4*)(smem + 352 + 2 * 4536);
    float* s_red  = (float*)s_B;                      // reused after mainloop

    const int tid = threadIdx.x, lane = tid & 31, w = tid >> 5;
    const int mg = w & 7, kh = w >> 3;
    const int tile = blockIdx.x, b = blockIdx.y;
    const int td = (tile >> 2) * 2, th = ((tile >> 1) & 1) * 8, tw = (tile & 1) * 8;

    for (int t = tid; t < KTAPS; t += 512) {
        int kd = t / 49, r = t % 49, kht = r / 7, kw = r % 7;
        tapoff[t] = (t < 343) ? (kd * 504 + kht * 24 + kw) : 0;
    }

    const int c4 = lane & 3;
    const int m0 = mg * 16 + (lane >> 2), m1 = m0 + 8;
    const int g0 = (m0 >> 6) * 1008 + ((m0 >> 3) & 7) * 48 + (m0 & 7) * 2;
    const int g1 = (m1 >> 6) * 1008 + ((m1 >> 3) & 7) * 48 + (m1 & 7) * 2;

    const uint32_t inb = (uint32_t)__cvta_generic_to_shared(s_in);
    const uint32_t Bb  = (uint32_t)__cvta_generic_to_shared(s_B);

    auto stage = [&](int c) {
        int buf = c & 1;
        const float* src = g_P + ((size_t)b * IC + c) * PCH
                         + (2 * td) * (PH * PW) + (2 * th) * PW + (2 * tw);
        uint32_t dsti = inb + (uint32_t)buf * 4536 * 4;
        for (int i = tid; i < 189 * 6; i += 512) {
            int dd = i / 126, r2 = i - dd * 126, dh = r2 / 6, ch = r2 - dh * 6;
            CPA(dsti + ((dd * 21 + dh) * 24 + ch * 4) * 4,
                src + dd * (PH * PW) + dh * PW + ch * 4);
        }
        const uint4* bsrc = g_W + (size_t)c * BCH_U4;
        uint32_t dstb = Bb + (uint32_t)buf * BCH_U4 * 16;
        for (int i = tid; i < BCH_U4; i += 512) CPA(dstb + i * 16, bsrc + i);
    };

    float acc[8][4];
#pragma unroll
    for (int j = 0; j < 8; j++)
#pragma unroll
        for (int k = 0; k < 4; k++) acc[j][k] = 0.f;

    stage(0); CPC();
    stage(1); CPC();

    for (int c = 0; c < IC; c++) {
        if (c < IC - 1) CPW1(); else CPW0();
        __syncthreads();

        const float* si = s_in + (c & 1) * 4536;
        const uint4* Bc = s_B + (c & 1) * BCH_U4;

#pragma unroll 1
        for (int ql = 0; ql < 11; ql++) {
            const int q = kh * 11 + ql;
            const int* tq = tapoff + q * 16 + 2 * c4;
            int o0 = tq[0], o1 = tq[1], o2 = tq[8], o3 = tq[9];
            float f0 = si[g0 + o0], f1 = si[g0 + o1];
            float f2 = si[g1 + o0], f3 = si[g1 + o1];
            float f4 = si[g0 + o2], f5 = si[g0 + o3];
            float f6 = si[g1 + o2], f7 = si[g1 + o3];

            uint32_t ah[4], al[4];
            ah[0] = pack_bf16x2(f1, f0); ah[1] = pack_bf16x2(f3, f2);
            ah[2] = pack_bf16x2(f5, f4); ah[3] = pack_bf16x2(f7, f6);
            float hl, hh;
            unpack_bf16x2(ah[0], hl, hh); al[0] = pack_bf16x2(f1 - hh, f0 - hl);
            unpack_bf16x2(ah[1], hl, hh); al[1] = pack_bf16x2(f3 - hh, f2 - hl);
            unpack_bf16x2(ah[2], hl, hh); al[2] = pack_bf16x2(f5 - hh, f4 - hl);
            unpack_bf16x2(ah[3], hl, hh); al[3] = pack_bf16x2(f7 - hh, f6 - hl);

            const uint4* Bq = Bc + q * CHUNK_U4 + lane;
#pragma unroll
            for (int j = 0; j < 8; j++) {
                uint4 bb = Bq[j * 32];
                mma_bf16(acc[j], ah, bb.x, bb.y);   // Ah*Bh
                mma_bf16(acc[j], al, bb.x, bb.y);   // Al*Bh
                mma_bf16(acc[j], ah, bb.z, bb.w);   // Ah*Bl
            }
        }

        if (c + 2 < IC) {
            __syncthreads();
            stage(c + 2); CPC();
        }
    }

    // ---- K-half reduction: kh=1 warps park partials in smem, kh=0 adds ----
    __syncthreads();
    if (kh == 1) {
        float* dst = s_red + (mg * 32 + lane) * 32;
#pragma unroll
        for (int j = 0; j < 8; j++)
#pragma unroll
            for (int k = 0; k < 4; k++) dst[j * 4 + k] = acc[j][k];
    }
    __syncthreads();
    if (kh == 0) {
        const float* src = s_red + (mg * 32 + lane) * 32;
#pragma unroll
        for (int j = 0; j < 8; j++)
#pragma unroll
            for (int k = 0; k < 4; k++) acc[j][k] += src[j * 4 + k];

        const int od0 = td + (m0 >> 6), oh0 = th + ((m0 >> 3) & 7), ow0 = tw + (m0 & 7);
        const int od1 = td + (m1 >> 6), oh1 = th + ((m1 >> 3) & 7), ow1 = tw + (m1 & 7);
        float* ob = out + (size_t)b * OC * 4096;
        const int v0 = od0 * 256 + oh0 * 16 + ow0;
        const int v1 = od1 * 256 + oh1 * 16 + ow1;
#pragma unroll
        for (int j = 0; j < 8; j++) {
            int oc0 = j * 8 + 2 * c4;
            ob[(size_t)oc0 * 4096 + v0]       = acc[j][0];
            ob[(size_t)(oc0 + 1) * 4096 + v0] = acc[j][1];
            ob[(size_t)oc0 * 4096 + v1]       = acc[j][2];
            ob[(size_t)(oc0 + 1) * 4096 + v1] = acc[j][3];
        }
    }
}

// ---------------- epilogue kernels ----------------
__global__ void sumsq_kernel(const float* __restrict__ y) {
    __shared__ float red[256];
    const int ch = blockIdx.x, tid = threadIdx.x;
    float s = 0.f;
    for (int i = tid; i < 4 * 4096; i += 256) {
        int b = i >> 12, sp = i & 4095;
        float v = y[((size_t)b * OC + ch) * 4096 + sp];
        s = fmaf(v, v, s);
    }
    red[tid] = s;
    __syncthreads();
    for (int o = 128; o > 0; o >>= 1) {
        if (tid < o) red[tid] += red[tid + o];
        __syncthreads();
    }
    if (tid == 0) g_ss[ch] = red[0];
}

__global__ void finalize_kernel(const float* __restrict__ bngs, const float* __restrict__ bngv) {
    int ch = threadIdx.x;
    float sc;
    if (ch < 16) sc = bngs[ch] / sqrtf(g_ss[ch] / 16384.f + EPSV);
    else {
        int u = (ch - 16) / 3;
        sc = bngv[u] / sqrtf((g_ss[16 + 3 * u] + g_ss[17 + 3 * u] + g_ss[18 + 3 * u]) / 49152.f + EPSV);
    }
    g_scale[ch] = sc;
}

__global__ void scale_act_kernel(float* __restrict__ y, const float* __restrict__ bias) {
    int i = blockIdx.x * 256 + threadIdx.x;
    int ch = (i >> 12) & 63;
    float v = y[i] * g_scale[ch];
    if (ch < 16) v = fmaxf(v + bias[ch], 0.f);
    y[i] = v;
}

// ---------------- launch ----------------
extern "C" void kernel_launch(void* const* d_in, const int* in_sizes, int n_in,
                              void* d_out, int out_size) {
    const float* sv = (const float*)d_in[0];
    const float *wss, *wsv, *wst, *wvs, *wvv, *wvt;
    const float *bss, *bsv, *bst, *bvs, *bvv, *bvt;
    if (in_sizes[1] == 1029) {
        bss = (const float*)d_in[1];  wss = (const float*)d_in[2];
        bsv = (const float*)d_in[3];  wsv = (const float*)d_in[4];
        bst = (const float*)d_in[5];  wst = (const float*)d_in[6];
        bvs = (const float*)d_in[7];  wvs = (const float*)d_in[8];
        bvv = (const float*)d_in[9];  wvv = (const float*)d_in[10];
        bvt = (const float*)d_in[11]; wvt = (const float*)d_in[12];
    } else {
        wss = (const float*)d_in[1];  wsv = (const float*)d_in[2];  wst = (const float*)d_in[3];
        wvs = (const float*)d_in[4];  wvv = (const float*)d_in[5];  wvt = (const float*)d_in[6];
        bss = (const float*)d_in[7];  bsv = (const float*)d_in[8];  bst = (const float*)d_in[9];
        bvs = (const float*)d_in[10]; bvv = (const float*)d_in[11]; bvt = (const float*)d_in[12];
    }
    const float* bngs = (const float*)d_in[13];
    const float* bngv = (const float*)d_in[14];
    const float* bias = (const float*)d_in[15];
    float* out = (float*)d_out;

    const int SMEM_BYTES = (352 + 2 * 4536 + 2 * BCH_U4 * 4) * 4;   // 217,920 B
    cudaFuncSetAttribute(conv_kernel, cudaFuncAttributeMaxDynamicSharedMemorySize, SMEM_BYTES);

    int n1 = 104 * KTAPS * 64;
    build_w_kernel<<<(n1 + 255) / 256, 256>>>(0, 104, wss, wsv, wst, wvs, wvv, wvt,
                                              bss, bsv, bst, bvs, bvv, bvt);
    build_w_kernel<<<(n1 + 255) / 256, 256>>>(104, 208, wss, wsv, wst, wvs, wvv, wvt,
                                              bss, bsv, bst, bvs, bvv, bvt);
    long long nP = (long long)4 * IC * PCH;
    pad_kernel<<<(unsigned)((nP + 255) / 256), 256>>>(sv);
    conv_kernel<<<dim3(32, 4), 512, SMEM_BYTES>>>(out);
    sumsq_kernel<<<64, 256>>>(out);
    finalize_kernel<<<1, 64>>>(bngs, bngv);
    scale_act_kernel<<<4096, 256>>>(out, bias);
}